// round 11
// baseline (speedup 1.0000x reference)
#include <cuda_runtime.h>
#include <cuda_bf16.h>
#include <math.h>

#define NPTS   64              // interpolation intervals over s in [0, 10]
#define TAB_N  (NPTS + 4)      // 68: +1 guard below, +2 above (Catmull-Rom)
#define S_MAX  10.0f           // 1/sqrt(EPS2)
#define EPS2   0.01f
#define BLK    128             // threads per worker block

// g(s) = d(MLP)/ds at s_k = (k-1)*h, k = 0..NPTS+3
__device__ float g_table[TAB_N];
__device__ float minv_g[3];

// ---------------------------------------------------------------------------
// Kernel 1 (PDL primary): build the 1-D derivative table. One point per warp.
// Fused fwd+bwd: tot = sum_k g2_k * (W2 @ u)_k, u_j = W1_j * silu'(a1_j)
// -> ONE row-major pass over W2 (staged in smem, stride 129).
// ---------------------------------------------------------------------------
__global__ void build_table_kernel(const float* __restrict__ W1,
                                   const float* __restrict__ b1,
                                   const float* __restrict__ W2,
                                   const float* __restrict__ b2,
                                   const float* __restrict__ W3,
                                   const float* __restrict__ log_m)
{
    cudaTriggerProgrammaticLaunchCompletion();   // let hnn_kernel start now

    extern __shared__ float sm[];
    float* sW2  = sm;                       // [128][129]
    float* sbuf = sm + 128 * 129;           // per-warp: 128 h1 + 128 u

    const float4* W24 = (const float4*)W2;
    for (int idx = threadIdx.x; idx < 128 * 32; idx += blockDim.x) {
        const float4 v = W24[idx];
        float* d = sW2 + (idx >> 5) * 129 + ((idx & 31) << 2);
        d[0] = v.x; d[1] = v.y; d[2] = v.z; d[3] = v.w;
    }
    if (blockIdx.x == 0 && threadIdx.x < 3)
        minv_g[threadIdx.x] = 1.0f / (expf(log_m[threadIdx.x]) + 1e-8f);
    __syncthreads();

    const int warp = threadIdx.x >> 5;
    const int lane = threadIdx.x & 31;
    float* sh1 = sbuf + warp * 256;
    float* su  = sh1 + 128;

    const int nwarps = (blockDim.x >> 5) * gridDim.x;
    const int gw     = blockIdx.x * (blockDim.x >> 5) + warp;
    const float hstep = S_MAX / (float)NPTS;

    for (int pt = gw; pt < TAB_N; pt += nwarps) {
        const float s = (float)(pt - 1) * hstep;

        #pragma unroll
        for (int m = 0; m < 4; m++) {
            const int j = lane + 32 * m;
            const float w  = W1[j];
            const float a  = fmaf(w, s, b1[j]);
            const float sg = 1.0f / (1.0f + __expf(-a));
            sh1[j] = a * sg;
            su[j]  = w * sg * (1.0f + a * (1.0f - sg));
        }
        __syncwarp();

        float acch0 = b2[lane], acch1 = b2[lane + 32],
              acch2 = b2[lane + 64], acch3 = b2[lane + 96];
        float accu0 = 0.f, accu1 = 0.f, accu2 = 0.f, accu3 = 0.f;
        const float* w0 = sW2 + lane * 129;
        #pragma unroll 4
        for (int j = 0; j < 128; j++) {
            const float hj = sh1[j];
            const float uj = su[j];
            const float wa = w0[j];
            const float wb = w0[32 * 129 + j];
            const float wc = w0[64 * 129 + j];
            const float wd = w0[96 * 129 + j];
            acch0 = fmaf(wa, hj, acch0);  accu0 = fmaf(wa, uj, accu0);
            acch1 = fmaf(wb, hj, acch1);  accu1 = fmaf(wb, uj, accu1);
            acch2 = fmaf(wc, hj, acch2);  accu2 = fmaf(wc, uj, accu2);
            acch3 = fmaf(wd, hj, acch3);  accu3 = fmaf(wd, uj, accu3);
        }

        float tot = 0.0f;
        #pragma unroll
        for (int m = 0; m < 4; m++) {
            const float a  = (m == 0) ? acch0 : (m == 1) ? acch1 : (m == 2) ? acch2 : acch3;
            const float au = (m == 0) ? accu0 : (m == 1) ? accu1 : (m == 2) ? accu2 : accu3;
            const float sg = 1.0f / (1.0f + __expf(-a));
            tot = fmaf(W3[lane + 32 * m] * sg * (1.0f + a * (1.0f - sg)), au, tot);
        }
        #pragma unroll
        for (int off = 16; off; off >>= 1)
            tot += __shfl_xor_sync(0xffffffffu, tot, off);
        if (lane == 0) g_table[pt] = tot;
        __syncwarp();
    }
}

// Catmull-Rom lookup of g(s) from a shared-memory table
__device__ __forceinline__ float lookup_g(const float* __restrict__ tab, float s)
{
    const float inv_h = (float)NPTS / S_MAX;
    const float u = s * inv_h;
    int i = (int)u;
    if (i > NPTS - 1) i = NPTS - 1;
    const float t  = u - (float)i;
    const float p0 = tab[i];
    const float p1 = tab[i + 1];
    const float p2 = tab[i + 2];
    const float p3 = tab[i + 3];
    return p1 + 0.5f * t * ((p2 - p0)
           + t * ((2.0f * p0 - 5.0f * p1 + 4.0f * p2 - p3)
           + t * (3.0f * (p1 - p2) + (p3 - p0))));
}

// per-sample physics on an 18-float register row (in: q,p ; out: dq, dp)
__device__ __forceinline__ void sample_physics(float* __restrict__ zz,
                                               const float* __restrict__ tab,
                                               float mi0, float mi1, float mi2)
{
    float q[9], p[9], f[9];
    #pragma unroll
    for (int c = 0; c < 9; c++) { q[c] = zz[c]; p[c] = zz[9 + c]; }
    #pragma unroll
    for (int c = 0; c < 3; c++) {
        zz[c]     = p[c]     * mi0;          // dq/dt
        zz[3 + c] = p[3 + c] * mi1;
        zz[6 + c] = p[6 + c] * mi2;
    }
    #pragma unroll
    for (int c = 0; c < 9; c++) f[c] = 0.0f;

    const int PI[3] = {0, 0, 1};
    const int PJ[3] = {1, 2, 2};
    #pragma unroll
    for (int pr = 0; pr < 3; pr++) {
        const int bi = PI[pr] * 3, bj = PJ[pr] * 3;
        const float dx = q[bi]     - q[bj];
        const float dy = q[bi + 1] - q[bj + 1];
        const float dz = q[bi + 2] - q[bj + 2];
        const float r2 = fmaf(dx, dx, fmaf(dy, dy, fmaf(dz, dz, EPS2)));
        const float s  = rsqrtf(r2);             // 1/d
        const float g  = lookup_g(tab, s);       // dV_pair/ds
        const float w  = g * s * s * s;          // g / d^3
        f[bi]     += w * dx;  f[bi + 1] += w * dy;  f[bi + 2] += w * dz;
        f[bj]     -= w * dx;  f[bj + 1] -= w * dy;  f[bj + 2] -= w * dz;
    }
    #pragma unroll
    for (int c = 0; c < 9; c++) zz[9 + c] = f[c];   // dp/dt
}

// ---------------------------------------------------------------------------
// Kernel 2 (PDL secondary): register-direct, NO smem staging, NO barriers
// (except table copy sync). Two samples per thread = 144 B = 9 aligned
// float4: load 9x LDG.128 -> compute both samples in registers -> 9x STG.128.
// Loads are issued before the grid-dependency wait so they overlap the
// table build.
// ---------------------------------------------------------------------------
__global__ void __launch_bounds__(BLK) hnn_kernel(const float4* __restrict__ z4,
                                                  float4* __restrict__ out4, int B)
{
    __shared__ float s_tab[TAB_N];

    const int tid    = threadIdx.x;
    const int pair   = blockIdx.x * BLK + tid;   // samples 2*pair, 2*pair+1
    const int npairs = B >> 1;
    const bool active = pair < npairs;

    // ---- load 2 samples (9 float4) straight into registers ----
    float4 v[9];
    if (active) {
        const float4* src = z4 + (size_t)pair * 9;
        #pragma unroll
        for (int i = 0; i < 9; i++) v[i] = src[i];
    }

    // wait for the table-builder grid (HW dependency; no-op if serialized)
    cudaGridDependencySynchronize();

    for (int i = tid; i < TAB_N; i += BLK) s_tab[i] = g_table[i];
    const float mi0 = minv_g[0], mi1 = minv_g[1], mi2 = minv_g[2];
    __syncthreads();

    if (active) {
        float a[36];
        #pragma unroll
        for (int i = 0; i < 9; i++) {
            a[4 * i]     = v[i].x;  a[4 * i + 1] = v[i].y;
            a[4 * i + 2] = v[i].z;  a[4 * i + 3] = v[i].w;
        }

        sample_physics(a,      s_tab, mi0, mi1, mi2);   // sample 2*pair
        sample_physics(a + 18, s_tab, mi0, mi1, mi2);   // sample 2*pair+1

        float4* dst = out4 + (size_t)pair * 9;
        #pragma unroll
        for (int i = 0; i < 9; i++)
            dst[i] = make_float4(a[4 * i], a[4 * i + 1], a[4 * i + 2], a[4 * i + 3]);
    }

    // odd-B tail: one extra sample handled scalar by the thread after the last pair
    if ((B & 1) && pair == npairs) {
        const float* zs = (const float*)z4;
        float a[18];
        #pragma unroll
        for (int c = 0; c < 18; c++) a[c] = zs[(size_t)(B - 1) * 18 + c];
        sample_physics(a, s_tab, mi0, mi1, mi2);
        float* os = (float*)out4;
        #pragma unroll
        for (int c = 0; c < 18; c++) os[(size_t)(B - 1) * 18 + c] = a[c];
    }
}

extern "C" void kernel_launch(void* const* d_in, const int* in_sizes, int n_in,
                              void* d_out, int out_size)
{
    const float* z     = (const float*)d_in[0];
    const float* log_m = (const float*)d_in[1];
    const float* W1    = (const float*)d_in[2];
    const float* b1    = (const float*)d_in[3];
    const float* W2    = (const float*)d_in[4];
    const float* b2    = (const float*)d_in[5];
    const float* W3    = (const float*)d_in[6];
    // d_in[7] = b3 drops out of the gradient
    float* out = (float*)d_out;
    const int B = in_sizes[0] / 18;

    const size_t smem = (128 * 129 + 8 * 256) * sizeof(float);  // 74240 B
    cudaFuncSetAttribute(build_table_kernel,
                         cudaFuncAttributeMaxDynamicSharedMemorySize, (int)smem);

    // primary: 9 blocks x 8 warps = 72 warps >= 68 table points
    build_table_kernel<<<9, 256, smem>>>(W1, b1, W2, b2, W3, log_m);

    // secondary with programmatic dependent launch: overlaps primary
    const int npairs = (B >> 1) + (B & 1);               // pair slots (+tail)
    const int grid   = (npairs + BLK - 1) / BLK;         // 1024 for B=262144

    cudaLaunchAttribute attrs[1];
    attrs[0].id = cudaLaunchAttributeProgrammaticStreamSerialization;
    attrs[0].val.programmaticStreamSerializationAllowed = 1;

    cudaLaunchConfig_t cfg = {};
    cfg.gridDim  = dim3(grid, 1, 1);
    cfg.blockDim = dim3(BLK, 1, 1);
    cfg.dynamicSmemBytes = 0;
    cfg.stream = 0;
    cfg.attrs = attrs;
    cfg.numAttrs = 1;

    cudaLaunchKernelEx(&cfg, hnn_kernel, (const float4*)z, (float4*)out, B);
}

// round 13
// speedup vs baseline: 1.4076x; 1.4076x over previous
#include <cuda_runtime.h>
#include <cuda_bf16.h>
#include <cuda_pipeline.h>
#include <math.h>

#define NPTS   64              // interpolation intervals over s in [0, 10]
#define TAB_N  (NPTS + 4)      // 68: +1 guard below, +2 above (Catmull-Rom)
#define S_MAX  10.0f           // 1/sqrt(EPS2)
#define EPS2   0.01f
#define BLK    128             // threads per worker block
#define SPB    128             // samples per tile
#define TILES  2               // tiles per worker block (both prefetched up front)

// g(s) = d(MLP)/ds at s_k = (k-1)*h, k = 0..NPTS+3
__device__ float g_table[TAB_N];
__device__ float minv_g[3];

// ---------------------------------------------------------------------------
// Kernel 1 (PDL primary): ONE BLOCK PER TABLE POINT (68 blocks, 128 threads).
// Thread k owns output row k of W2. Fused fwd+bwd:
//   tot = sum_k W3_k * silu'(a2_k) * (W2 @ u)_k,  u_j = W1_j * silu'(a1_j)
// W2 staged as 32 float4 PER THREAD (128 threads x 32 = 4096 float4 = all of
// W2; R12's bug was 16/thread = half the matrix).
// ---------------------------------------------------------------------------
__global__ void build_table_kernel(const float* __restrict__ W1,
                                   const float* __restrict__ b1,
                                   const float* __restrict__ W2,
                                   const float* __restrict__ b2,
                                   const float* __restrict__ W3,
                                   const float* __restrict__ log_m)
{
    cudaTriggerProgrammaticLaunchCompletion();   // let hnn_kernel start now

    extern __shared__ float sm[];
    float* sW2 = sm;                 // [128][129]
    float* sh1 = sm + 128 * 129;     // 128
    float* su  = sh1 + 128;          // 128
    float* red = su  + 128;          // 4

    const int tid = threadIdx.x;     // 0..127 == output row k
    const int pt  = blockIdx.x;      // 0..TAB_N-1

    if (pt == 0 && tid < 3)
        minv_g[tid] = 1.0f / (expf(log_m[tid]) + 1e-8f);

    // layer 1 for this point: h1[tid], u[tid]
    const float hstep = S_MAX / (float)NPTS;
    const float s = (float)(pt - 1) * hstep;
    {
        const float w  = W1[tid];
        const float a  = fmaf(w, s, b1[tid]);
        const float sg = 1.0f / (1.0f + __expf(-a));
        sh1[tid] = a * sg;
        su[tid]  = w * sg * (1.0f + a * (1.0f - sg));
    }

    // stage ALL of W2 (4096 float4) padded to stride 129: 32 float4 per thread
    const float4* W24 = (const float4*)W2;
    #pragma unroll
    for (int r = 0; r < 32; r++) {
        const int idx = tid + r * 128;              // 0..4095
        const float4 v = W24[idx];
        float* d = sW2 + (idx >> 5) * 129 + ((idx & 31) << 2);
        d[0] = v.x; d[1] = v.y; d[2] = v.z; d[3] = v.w;
    }
    __syncthreads();

    // row-k dot products: acch = (W2@h1)_k + b2_k,  accu = (W2@u)_k
    float acch = b2[tid], accu = 0.0f;
    const float* wr = sW2 + tid * 129;
    #pragma unroll 8
    for (int j = 0; j < 128; j++) {
        const float w = wr[j];
        acch = fmaf(w, sh1[j], acch);
        accu = fmaf(w, su[j], accu);
    }
    const float sg  = 1.0f / (1.0f + __expf(-acch));
    float val = W3[tid] * sg * (1.0f + acch * (1.0f - sg)) * accu;

    // block reduction: warp shuffle -> 4 partials -> thread 0
    #pragma unroll
    for (int off = 16; off; off >>= 1)
        val += __shfl_xor_sync(0xffffffffu, val, off);
    if ((tid & 31) == 0) red[tid >> 5] = val;
    __syncthreads();
    if (tid == 0) g_table[pt] = red[0] + red[1] + red[2] + red[3];
}

// Catmull-Rom lookup of g(s) from a shared-memory table
__device__ __forceinline__ float lookup_g(const float* __restrict__ tab, float s)
{
    const float inv_h = (float)NPTS / S_MAX;
    const float u = s * inv_h;
    int i = (int)u;
    if (i > NPTS - 1) i = NPTS - 1;
    const float t  = u - (float)i;
    const float p0 = tab[i];
    const float p1 = tab[i + 1];
    const float p2 = tab[i + 2];
    const float p3 = tab[i + 3];
    return p1 + 0.5f * t * ((p2 - p0)
           + t * ((2.0f * p0 - 5.0f * p1 + 4.0f * p2 - p3)
           + t * (3.0f * (p1 - p2) + (p3 - p0))));
}

// ---------------------------------------------------------------------------
// Kernel 2 (PDL secondary): R8-best structure. Both tiles prefetched with
// cp.async BEFORE the grid-dependency wait (overlaps the table build), one
// compute barrier phase, coalesced float4 smem-staged I/O.
// ---------------------------------------------------------------------------
__global__ void __launch_bounds__(BLK) hnn_kernel(const float* __restrict__ z,
                                                  float* __restrict__ out, int B)
{
    __shared__ __align__(16) float sbuf[TILES][SPB * 18];  // 18432 B
    __shared__ __align__(16) float s_tab[TAB_N];
    __shared__ float s_minv[3];

    const int tid = threadIdx.x;
    const int ntiles_tot = (B + SPB - 1) / SPB;
    const int tile0 = blockIdx.x * TILES;

    // prefetch both tiles (independent of the primary kernel)
    #pragma unroll
    for (int t = 0; t < TILES; t++) {
        const int tile = tile0 + t;
        if (tile < ntiles_tot) {
            const int nelem = min(SPB, B - tile * SPB) * 18;
            const float* src = z + (size_t)tile * (SPB * 18);
            float* dst = sbuf[t];
            const int n4 = nelem >> 2;
            for (int i = tid; i < n4; i += BLK)
                __pipeline_memcpy_async(dst + 4 * i, src + 4 * i, 16);
            for (int i = (n4 << 2) + tid; i < nelem; i += BLK)
                __pipeline_memcpy_async(dst + i, src + i, 4);
        }
    }
    __pipeline_commit();

    // wait for the table-builder grid (HW dependency; no-op if serialized)
    cudaGridDependencySynchronize();

    for (int i = tid; i < TAB_N; i += BLK) s_tab[i] = g_table[i];
    if (tid < 3) s_minv[tid] = minv_g[tid];

    __pipeline_wait_prior(0);
    __syncthreads();

    const float mi0 = s_minv[0], mi1 = s_minv[1], mi2 = s_minv[2];

    // compute both tiles in one barrier phase
    #pragma unroll
    for (int t = 0; t < TILES; t++) {
        const int tile = tile0 + t;
        if (tile >= ntiles_tot) break;
        const int nrows = min(SPB, B - tile * SPB);
        if (tid < nrows) {
            float* r = sbuf[t] + tid * 18;
            float q[9], p[9], f[9];
            #pragma unroll
            for (int c = 0; c < 9; c++) { q[c] = r[c]; p[c] = r[9 + c]; }
            #pragma unroll
            for (int c = 0; c < 3; c++) {
                r[c]     = p[c]     * mi0;      // dq/dt
                r[3 + c] = p[3 + c] * mi1;
                r[6 + c] = p[6 + c] * mi2;
            }
            #pragma unroll
            for (int c = 0; c < 9; c++) f[c] = 0.0f;

            const int PI[3] = {0, 0, 1};
            const int PJ[3] = {1, 2, 2};
            #pragma unroll
            for (int pr = 0; pr < 3; pr++) {
                const int bi = PI[pr] * 3, bj = PJ[pr] * 3;
                const float dx = q[bi]     - q[bj];
                const float dy = q[bi + 1] - q[bj + 1];
                const float dz = q[bi + 2] - q[bj + 2];
                const float r2 = fmaf(dx, dx, fmaf(dy, dy, fmaf(dz, dz, EPS2)));
                const float s  = rsqrtf(r2);            // 1/d
                const float g  = lookup_g(s_tab, s);    // dV_pair/ds
                const float w  = g * s * s * s;         // g / d^3
                f[bi]     += w * dx;  f[bi + 1] += w * dy;  f[bi + 2] += w * dz;
                f[bj]     -= w * dx;  f[bj + 1] -= w * dy;  f[bj + 2] -= w * dz;
            }
            #pragma unroll
            for (int c = 0; c < 9; c++) r[9 + c] = f[c];   // dp/dt
        }
    }
    __syncthreads();

    // store both tiles, fully coalesced
    #pragma unroll
    for (int t = 0; t < TILES; t++) {
        const int tile = tile0 + t;
        if (tile >= ntiles_tot) break;
        const int nelem = min(SPB, B - tile * SPB) * 18;
        const int n4 = nelem >> 2;
        float* dg = out + (size_t)tile * (SPB * 18);
        float4* o4 = (float4*)dg;
        const float4* s4 = (const float4*)sbuf[t];
        for (int i = tid; i < n4; i += BLK) o4[i] = s4[i];
        for (int i = (n4 << 2) + tid; i < nelem; i += BLK) dg[i] = sbuf[t][i];
    }
}

extern "C" void kernel_launch(void* const* d_in, const int* in_sizes, int n_in,
                              void* d_out, int out_size)
{
    const float* z     = (const float*)d_in[0];
    const float* log_m = (const float*)d_in[1];
    const float* W1    = (const float*)d_in[2];
    const float* b1    = (const float*)d_in[3];
    const float* W2    = (const float*)d_in[4];
    const float* b2    = (const float*)d_in[5];
    const float* W3    = (const float*)d_in[6];
    // d_in[7] = b3 drops out of the gradient
    float* out = (float*)d_out;
    const int B = in_sizes[0] / 18;

    const size_t smem = (128 * 129 + 128 + 128 + 4) * sizeof(float);  // 67088 B
    cudaFuncSetAttribute(build_table_kernel,
                         cudaFuncAttributeMaxDynamicSharedMemorySize, (int)smem);

    // primary: one block per table point
    build_table_kernel<<<TAB_N, 128, smem>>>(W1, b1, W2, b2, W3, log_m);

    // secondary with programmatic dependent launch: overlaps primary
    const int ntiles = (B + SPB - 1) / SPB;              // 2048
    const int grid   = (ntiles + TILES - 1) / TILES;     // 1024

    cudaLaunchAttribute attrs[1];
    attrs[0].id = cudaLaunchAttributeProgrammaticStreamSerialization;
    attrs[0].val.programmaticStreamSerializationAllowed = 1;

    cudaLaunchConfig_t cfg = {};
    cfg.gridDim  = dim3(grid, 1, 1);
    cfg.blockDim = dim3(BLK, 1, 1);
    cfg.dynamicSmemBytes = 0;
    cfg.stream = 0;
    cfg.attrs = attrs;
    cfg.numAttrs = 1;

    cudaLaunchKernelEx(&cfg, hnn_kernel, z, out, B);
}

// round 14
// speedup vs baseline: 1.4636x; 1.0397x over previous
#include <cuda_runtime.h>
#include <cuda_bf16.h>
#include <math.h>

#define NPTS   64              // interpolation intervals over s in [0, 10]
#define TAB_N  (NPTS + 4)      // 68: +1 guard below, +2 above (Catmull-Rom)
#define S_MAX  10.0f           // 1/sqrt(EPS2)
#define EPS2   0.01f
#define BLK    128             // threads per worker block
#define SPB    128             // samples per tile
#define TILES  2               // tiles per worker block
#define TILE_BYTES (SPB * 18 * 4)   // 9216 B, 16B-multiple

// g(s) = d(MLP)/ds at s_k = (k-1)*h, k = 0..NPTS+3
__device__ float g_table[TAB_N];
__device__ float minv_g[3];

__device__ __forceinline__ unsigned smem_u32(const void* p) {
    unsigned a;
    asm("{ .reg .u64 t; cvta.to.shared.u64 t, %1; cvt.u32.u64 %0, t; }"
        : "=r"(a) : "l"(p));
    return a;
}

__device__ __forceinline__ void mbar_wait(unsigned mbar, unsigned parity) {
    asm volatile(
        "{\n\t.reg .pred P;\n\t"
        "W%=:\n\t"
        "mbarrier.try_wait.parity.shared.b64 P, [%0], %1;\n\t"
        "@P bra D%=;\n\t"
        "bra W%=;\n\t"
        "D%=:\n\t}"
        :: "r"(mbar), "r"(parity) : "memory");
}

// ---------------------------------------------------------------------------
// Kernel 1 (PDL primary): one block per table point (68 x 128 threads).
// Thread k owns W2 row k. Fused fwd+bwd:
//   tot = sum_k W3_k * silu'(a2_k) * (W2 @ u)_k,  u_j = W1_j * silu'(a1_j)
// ---------------------------------------------------------------------------
__global__ void build_table_kernel(const float* __restrict__ W1,
                                   const float* __restrict__ b1,
                                   const float* __restrict__ W2,
                                   const float* __restrict__ b2,
                                   const float* __restrict__ W3,
                                   const float* __restrict__ log_m)
{
    cudaTriggerProgrammaticLaunchCompletion();   // let hnn_kernel start now

    extern __shared__ float sm[];
    float* sW2 = sm;                 // [128][129]
    float* sh1 = sm + 128 * 129;     // 128
    float* su  = sh1 + 128;          // 128
    float* red = su  + 128;          // 4

    const int tid = threadIdx.x;     // 0..127 == output row k
    const int pt  = blockIdx.x;      // 0..TAB_N-1

    if (pt == 0 && tid < 3)
        minv_g[tid] = 1.0f / (expf(log_m[tid]) + 1e-8f);

    const float hstep = S_MAX / (float)NPTS;
    const float s = (float)(pt - 1) * hstep;
    {
        const float w  = W1[tid];
        const float a  = fmaf(w, s, b1[tid]);
        const float sg = 1.0f / (1.0f + __expf(-a));
        sh1[tid] = a * sg;
        su[tid]  = w * sg * (1.0f + a * (1.0f - sg));
    }

    // stage ALL of W2 (4096 float4), padded stride 129: 32 float4 per thread
    const float4* W24 = (const float4*)W2;
    #pragma unroll
    for (int r = 0; r < 32; r++) {
        const int idx = tid + r * 128;              // 0..4095
        const float4 v = W24[idx];
        float* d = sW2 + (idx >> 5) * 129 + ((idx & 31) << 2);
        d[0] = v.x; d[1] = v.y; d[2] = v.z; d[3] = v.w;
    }
    __syncthreads();

    float acch = b2[tid], accu = 0.0f;
    const float* wr = sW2 + tid * 129;
    #pragma unroll 8
    for (int j = 0; j < 128; j++) {
        const float w = wr[j];
        acch = fmaf(w, sh1[j], acch);
        accu = fmaf(w, su[j], accu);
    }
    const float sg  = 1.0f / (1.0f + __expf(-acch));
    float val = W3[tid] * sg * (1.0f + acch * (1.0f - sg)) * accu;

    #pragma unroll
    for (int off = 16; off; off >>= 1)
        val += __shfl_xor_sync(0xffffffffu, val, off);
    if ((tid & 31) == 0) red[tid >> 5] = val;
    __syncthreads();
    if (tid == 0) g_table[pt] = red[0] + red[1] + red[2] + red[3];
}

// Catmull-Rom lookup of g(s) from a shared-memory table
__device__ __forceinline__ float lookup_g(const float* __restrict__ tab, float s)
{
    const float inv_h = (float)NPTS / S_MAX;
    const float u = s * inv_h;
    int i = (int)u;
    if (i > NPTS - 1) i = NPTS - 1;
    const float t  = u - (float)i;
    const float p0 = tab[i];
    const float p1 = tab[i + 1];
    const float p2 = tab[i + 2];
    const float p3 = tab[i + 3];
    return p1 + 0.5f * t * ((p2 - p0)
           + t * ((2.0f * p0 - 5.0f * p1 + 4.0f * p2 - p3)
           + t * (3.0f * (p1 - p2) + (p3 - p0))));
}

// ---------------------------------------------------------------------------
// Kernel 2 (PDL secondary): BULK-COPY staging. Stage-in via cp.async.bulk
// (2 instructions instead of ~1152 LDGSTS/block), stage-out via
// cp.async.bulk.global.shared (2 instructions instead of ~1152 LDS/STG).
// Compute phase unchanged. Bulk loads issue BEFORE the PDL wait.
// ---------------------------------------------------------------------------
__global__ void __launch_bounds__(BLK) hnn_kernel(const float* __restrict__ z,
                                                  float* __restrict__ out, int B)
{
    __shared__ __align__(16) float sbuf[TILES][SPB * 18];  // 18432 B
    __shared__ __align__(16) float s_tab[TAB_N];
    __shared__ __align__(8)  unsigned long long mbar;
    __shared__ float s_minv[3];

    const int tid = threadIdx.x;
    const int ntiles_tot = (B + SPB - 1) / SPB;
    const int tile0 = blockIdx.x * TILES;
    const unsigned mb = smem_u32(&mbar);

    // how many full tiles can go through the bulk path
    int nfull = 0;
    unsigned total_tx = 0;
    #pragma unroll
    for (int t = 0; t < TILES; t++) {
        const int tile = tile0 + t;
        if (tile < ntiles_tot && min(SPB, B - tile * SPB) == SPB) {
            nfull++; total_tx += TILE_BYTES;
        }
    }

    // ---- bulk stage-in (independent of the primary kernel) ----
    if (tid == 0) {
        asm volatile("mbarrier.init.shared.b64 [%0], 1;" :: "r"(mb) : "memory");
        asm volatile("fence.proxy.async.shared::cta;" ::: "memory");
        if (nfull > 0)
            asm volatile("mbarrier.arrive.expect_tx.shared.b64 _, [%0], %1;"
                         :: "r"(mb), "r"(total_tx) : "memory");
        for (int t = 0; t < nfull; t++) {
            const int tile = tile0 + t;
            asm volatile(
                "cp.async.bulk.shared::cta.global.mbarrier::complete_tx::bytes "
                "[%0], [%1], %2, [%3];"
                :: "r"(smem_u32(sbuf[t])),
                   "l"(z + (size_t)tile * (SPB * 18)),
                   "r"((unsigned)TILE_BYTES), "r"(mb)
                : "memory");
        }
    }

    // partial tiles (tail): plain loads
    for (int t = nfull; t < TILES; t++) {
        const int tile = tile0 + t;
        if (tile < ntiles_tot) {
            const int nelem = min(SPB, B - tile * SPB) * 18;
            const float* src = z + (size_t)tile * (SPB * 18);
            for (int i = tid; i < nelem; i += BLK) sbuf[t][i] = src[i];
        }
    }

    // wait for the table-builder grid (HW dependency; no-op if serialized)
    cudaGridDependencySynchronize();

    for (int i = tid; i < TAB_N; i += BLK) s_tab[i] = g_table[i];
    if (tid < 3) s_minv[tid] = minv_g[tid];
    __syncthreads();                 // mbar init + table visible to all
    if (nfull > 0) mbar_wait(mb, 0); // bulk data landed

    const float mi0 = s_minv[0], mi1 = s_minv[1], mi2 = s_minv[2];

    // compute both tiles in one barrier phase
    #pragma unroll
    for (int t = 0; t < TILES; t++) {
        const int tile = tile0 + t;
        if (tile >= ntiles_tot) break;
        const int nrows = min(SPB, B - tile * SPB);
        if (tid < nrows) {
            float* r = sbuf[t] + tid * 18;
            float q[9], p[9], f[9];
            #pragma unroll
            for (int c = 0; c < 9; c++) { q[c] = r[c]; p[c] = r[9 + c]; }
            #pragma unroll
            for (int c = 0; c < 3; c++) {
                r[c]     = p[c]     * mi0;      // dq/dt
                r[3 + c] = p[3 + c] * mi1;
                r[6 + c] = p[6 + c] * mi2;
            }
            #pragma unroll
            for (int c = 0; c < 9; c++) f[c] = 0.0f;

            const int PI[3] = {0, 0, 1};
            const int PJ[3] = {1, 2, 2};
            #pragma unroll
            for (int pr = 0; pr < 3; pr++) {
                const int bi = PI[pr] * 3, bj = PJ[pr] * 3;
                const float dx = q[bi]     - q[bj];
                const float dy = q[bi + 1] - q[bj + 1];
                const float dz = q[bi + 2] - q[bj + 2];
                const float r2 = fmaf(dx, dx, fmaf(dy, dy, fmaf(dz, dz, EPS2)));
                const float s  = rsqrtf(r2);            // 1/d
                const float g  = lookup_g(s_tab, s);    // dV_pair/ds
                const float w  = g * s * s * s;         // g / d^3
                f[bi]     += w * dx;  f[bi + 1] += w * dy;  f[bi + 2] += w * dz;
                f[bj]     -= w * dx;  f[bj + 1] -= w * dy;  f[bj + 2] -= w * dz;
            }
            #pragma unroll
            for (int c = 0; c < 9; c++) r[9 + c] = f[c];   // dp/dt
        }
    }
    __syncthreads();

    // ---- bulk stage-out ----
    if (tid == 0) {
        asm volatile("fence.proxy.async.shared::cta;" ::: "memory");
        for (int t = 0; t < nfull; t++) {
            const int tile = tile0 + t;
            asm volatile(
                "cp.async.bulk.global.shared::cta.bulk_group [%0], [%1], %2;"
                :: "l"(out + (size_t)tile * (SPB * 18)),
                   "r"(smem_u32(sbuf[t])), "r"((unsigned)TILE_BYTES)
                : "memory");
        }
        asm volatile("cp.async.bulk.commit_group;" ::: "memory");
        asm volatile("cp.async.bulk.wait_group 0;" ::: "memory");
    }

    // partial-tile stores
    for (int t = nfull; t < TILES; t++) {
        const int tile = tile0 + t;
        if (tile < ntiles_tot) {
            const int nelem = min(SPB, B - tile * SPB) * 18;
            float* dg = out + (size_t)tile * (SPB * 18);
            for (int i = tid; i < nelem; i += BLK) dg[i] = sbuf[t][i];
        }
    }
}

extern "C" void kernel_launch(void* const* d_in, const int* in_sizes, int n_in,
                              void* d_out, int out_size)
{
    const float* z     = (const float*)d_in[0];
    const float* log_m = (const float*)d_in[1];
    const float* W1    = (const float*)d_in[2];
    const float* b1    = (const float*)d_in[3];
    const float* W2    = (const float*)d_in[4];
    const float* b2    = (const float*)d_in[5];
    const float* W3    = (const float*)d_in[6];
    // d_in[7] = b3 drops out of the gradient
    float* out = (float*)d_out;
    const int B = in_sizes[0] / 18;

    const size_t smem = (128 * 129 + 128 + 128 + 4) * sizeof(float);  // 67088 B
    cudaFuncSetAttribute(build_table_kernel,
                         cudaFuncAttributeMaxDynamicSharedMemorySize, (int)smem);

    // primary: one block per table point
    build_table_kernel<<<TAB_N, 128, smem>>>(W1, b1, W2, b2, W3, log_m);

    // secondary with programmatic dependent launch: overlaps primary
    const int ntiles = (B + SPB - 1) / SPB;              // 2048
    const int grid   = (ntiles + TILES - 1) / TILES;     // 1024

    cudaLaunchAttribute attrs[1];
    attrs[0].id = cudaLaunchAttributeProgrammaticStreamSerialization;
    attrs[0].val.programmaticStreamSerializationAllowed = 1;

    cudaLaunchConfig_t cfg = {};
    cfg.gridDim  = dim3(grid, 1, 1);
    cfg.blockDim = dim3(BLK, 1, 1);
    cfg.dynamicSmemBytes = 0;
    cfg.stream = 0;
    cfg.attrs = attrs;
    cfg.numAttrs = 1;

    cudaLaunchKernelEx(&cfg, hnn_kernel, z, out, B);
}

// round 15
// speedup vs baseline: 1.4733x; 1.0067x over previous
#include <cuda_runtime.h>
#include <cuda_bf16.h>
#include <math.h>

#define NPTS   64              // interpolation intervals over s in [0, 10]
#define TAB_N  (NPTS + 4)      // 68: +1 guard below, +2 above (Catmull-Rom)
#define S_MAX  10.0f           // 1/sqrt(EPS2)
#define EPS2   0.01f
#define BLK    128             // threads per worker block
#define SPB    128             // samples per tile
#define TPB    4               // tiles per block (pipelined)
#define STAGES 3               // ring depth
#define TILE_BYTES (SPB * 18 * 4)   // 9216 B

// g(s) = d(MLP)/ds at s_k = (k-1)*h, k = 0..NPTS+3
__device__ float g_table[TAB_N];
__device__ float minv_g[3];

__device__ __forceinline__ unsigned smem_u32(const void* p) {
    unsigned a;
    asm("{ .reg .u64 t; cvta.to.shared.u64 t, %1; cvt.u32.u64 %0, t; }"
        : "=r"(a) : "l"(p));
    return a;
}

__device__ __forceinline__ void mbar_wait(unsigned mbar, unsigned parity) {
    asm volatile(
        "{\n\t.reg .pred P;\n\t"
        "W%=:\n\t"
        "mbarrier.try_wait.parity.shared.b64 P, [%0], %1;\n\t"
        "@P bra D%=;\n\t"
        "bra W%=;\n\t"
        "D%=:\n\t}"
        :: "r"(mbar), "r"(parity) : "memory");
}

// ---------------------------------------------------------------------------
// Kernel 1 (PDL primary): one block per table point (68 x 128 threads).
// Thread k owns W2 row k. Fused fwd+bwd:
//   tot = sum_k W3_k * silu'(a2_k) * (W2 @ u)_k,  u_j = W1_j * silu'(a1_j)
// ---------------------------------------------------------------------------
__global__ void build_table_kernel(const float* __restrict__ W1,
                                   const float* __restrict__ b1,
                                   const float* __restrict__ W2,
                                   const float* __restrict__ b2,
                                   const float* __restrict__ W3,
                                   const float* __restrict__ log_m)
{
    cudaTriggerProgrammaticLaunchCompletion();   // let hnn_kernel start now

    extern __shared__ float sm[];
    float* sW2 = sm;                 // [128][129]
    float* sh1 = sm + 128 * 129;     // 128
    float* su  = sh1 + 128;          // 128
    float* red = su  + 128;          // 4

    const int tid = threadIdx.x;     // 0..127 == output row k
    const int pt  = blockIdx.x;      // 0..TAB_N-1

    if (pt == 0 && tid < 3)
        minv_g[tid] = 1.0f / (expf(log_m[tid]) + 1e-8f);

    const float hstep = S_MAX / (float)NPTS;
    const float s = (float)(pt - 1) * hstep;
    {
        const float w  = W1[tid];
        const float a  = fmaf(w, s, b1[tid]);
        const float sg = 1.0f / (1.0f + __expf(-a));
        sh1[tid] = a * sg;
        su[tid]  = w * sg * (1.0f + a * (1.0f - sg));
    }

    // stage ALL of W2 (4096 float4), padded stride 129: 32 float4 per thread
    const float4* W24 = (const float4*)W2;
    #pragma unroll
    for (int r = 0; r < 32; r++) {
        const int idx = tid + r * 128;              // 0..4095
        const float4 v = W24[idx];
        float* d = sW2 + (idx >> 5) * 129 + ((idx & 31) << 2);
        d[0] = v.x; d[1] = v.y; d[2] = v.z; d[3] = v.w;
    }
    __syncthreads();

    float acch = b2[tid], accu = 0.0f;
    const float* wr = sW2 + tid * 129;
    #pragma unroll 8
    for (int j = 0; j < 128; j++) {
        const float w = wr[j];
        acch = fmaf(w, sh1[j], acch);
        accu = fmaf(w, su[j], accu);
    }
    const float sg  = 1.0f / (1.0f + __expf(-acch));
    float val = W3[tid] * sg * (1.0f + acch * (1.0f - sg)) * accu;

    #pragma unroll
    for (int off = 16; off; off >>= 1)
        val += __shfl_xor_sync(0xffffffffu, val, off);
    if ((tid & 31) == 0) red[tid >> 5] = val;
    __syncthreads();
    if (tid == 0) g_table[pt] = red[0] + red[1] + red[2] + red[3];
}

// Catmull-Rom lookup of g(s) from a shared-memory table
__device__ __forceinline__ float lookup_g(const float* __restrict__ tab, float s)
{
    const float inv_h = (float)NPTS / S_MAX;
    const float u = s * inv_h;
    int i = (int)u;
    if (i > NPTS - 1) i = NPTS - 1;
    const float t  = u - (float)i;
    const float p0 = tab[i];
    const float p1 = tab[i + 1];
    const float p2 = tab[i + 2];
    const float p3 = tab[i + 3];
    return p1 + 0.5f * t * ((p2 - p0)
           + t * ((2.0f * p0 - 5.0f * p1 + 4.0f * p2 - p3)
           + t * (3.0f * (p1 - p2) + (p3 - p0))));
}

__device__ __forceinline__ void sample_row(float* __restrict__ r,
                                           const float* __restrict__ tab,
                                           float mi0, float mi1, float mi2)
{
    float q[9], p[9], f[9];
    #pragma unroll
    for (int c = 0; c < 9; c++) { q[c] = r[c]; p[c] = r[9 + c]; }
    #pragma unroll
    for (int c = 0; c < 3; c++) {
        r[c]     = p[c]     * mi0;          // dq/dt
        r[3 + c] = p[3 + c] * mi1;
        r[6 + c] = p[6 + c] * mi2;
    }
    #pragma unroll
    for (int c = 0; c < 9; c++) f[c] = 0.0f;
    const int PI[3] = {0, 0, 1};
    const int PJ[3] = {1, 2, 2};
    #pragma unroll
    for (int pr = 0; pr < 3; pr++) {
        const int bi = PI[pr] * 3, bj = PJ[pr] * 3;
        const float dx = q[bi]     - q[bj];
        const float dy = q[bi + 1] - q[bj + 1];
        const float dz = q[bi + 2] - q[bj + 2];
        const float r2 = fmaf(dx, dx, fmaf(dy, dy, fmaf(dz, dz, EPS2)));
        const float s  = rsqrtf(r2);            // 1/d
        const float g  = lookup_g(tab, s);      // dV_pair/ds
        const float w  = g * s * s * s;         // g / d^3
        f[bi]     += w * dx;  f[bi + 1] += w * dy;  f[bi + 2] += w * dz;
        f[bj]     -= w * dx;  f[bj + 1] -= w * dy;  f[bj + 2] -= w * dz;
    }
    #pragma unroll
    for (int c = 0; c < 9; c++) r[9 + c] = f[c];    // dp/dt
}

// ---------------------------------------------------------------------------
// Kernel 2 (PDL secondary): per-block 3-stage bulk-copy ring over 4 tiles.
// Prologue loads 2 tiles BEFORE the PDL wait. Each iteration: mbar wait ->
// compute -> async bulk store (no wait) -> gated reload of the freed slot.
// Store/load latency hides under compute of other tiles and blocks.
// ---------------------------------------------------------------------------
__global__ void __launch_bounds__(BLK) hnn_kernel(const float* __restrict__ z,
                                                  float* __restrict__ out, int B)
{
    __shared__ __align__(16) float sbuf[STAGES][SPB * 18];  // 27648 B
    __shared__ __align__(16) float s_tab[TAB_N];
    __shared__ __align__(8)  unsigned long long mbar[STAGES];
    __shared__ float s_minv[3];

    const int tid  = threadIdx.x;
    const int ntf  = B / SPB;                     // full tiles
    const int tile0 = blockIdx.x * TPB;
    const int nt   = max(0, min(TPB, ntf - tile0));
    const unsigned mb0 = smem_u32(mbar);

    // ---- init + prologue loads (independent of the primary kernel) ----
    if (tid == 0 && nt > 0) {
        #pragma unroll
        for (int s = 0; s < STAGES; s++)
            asm volatile("mbarrier.init.shared.b64 [%0], 1;"
                         :: "r"(mb0 + 8u * s) : "memory");
        asm volatile("fence.proxy.async.shared::cta;" ::: "memory");
        const int npro = min(STAGES - 1, nt);
        for (int k = 0; k < npro; k++) {
            asm volatile("mbarrier.arrive.expect_tx.shared.b64 _, [%0], %1;"
                         :: "r"(mb0 + 8u * k), "r"((unsigned)TILE_BYTES) : "memory");
            asm volatile(
                "cp.async.bulk.shared::cta.global.mbarrier::complete_tx::bytes "
                "[%0], [%1], %2, [%3];"
                :: "r"(smem_u32(sbuf[k])),
                   "l"(z + (size_t)(tile0 + k) * (SPB * 18)),
                   "r"((unsigned)TILE_BYTES), "r"(mb0 + 8u * k)
                : "memory");
        }
    }

    // wait for the table-builder grid (HW dependency; no-op if serialized)
    cudaGridDependencySynchronize();

    for (int i = tid; i < TAB_N; i += BLK) s_tab[i] = g_table[i];
    if (tid < 3) s_minv[tid] = minv_g[tid];
    __syncthreads();                  // table + mbar inits visible block-wide

    const float mi0 = s_minv[0], mi1 = s_minv[1], mi2 = s_minv[2];

    for (int t = 0; t < nt; t++) {
        const int s  = t % STAGES;
        const unsigned ph = (unsigned)((t / STAGES) & 1);
        mbar_wait(mb0 + 8u * s, ph);              // tile t landed

        sample_row(sbuf[s] + tid * 18, s_tab, mi0, mi1, mi2);
        __syncthreads();                          // all rows written

        if (tid == 0) {
            asm volatile("fence.proxy.async.shared::cta;" ::: "memory");
            asm volatile(
                "cp.async.bulk.global.shared::cta.bulk_group [%0], [%1], %2;"
                :: "l"(out + (size_t)(tile0 + t) * (SPB * 18)),
                   "r"(smem_u32(sbuf[s])), "r"((unsigned)TILE_BYTES)
                : "memory");
            asm volatile("cp.async.bulk.commit_group;" ::: "memory");

            const int u = t + STAGES - 1;         // tile to prefetch
            if (u < nt) {
                if (t >= 1)   // slot u%STAGES was stored from at iter t-1
                    asm volatile("cp.async.bulk.wait_group 1;" ::: "memory");
                const unsigned mbu = mb0 + 8u * (u % STAGES);
                asm volatile("mbarrier.arrive.expect_tx.shared.b64 _, [%0], %1;"
                             :: "r"(mbu), "r"((unsigned)TILE_BYTES) : "memory");
                asm volatile(
                    "cp.async.bulk.shared::cta.global.mbarrier::complete_tx::bytes "
                    "[%0], [%1], %2, [%3];"
                    :: "r"(smem_u32(sbuf[u % STAGES])),
                       "l"(z + (size_t)(tile0 + u) * (SPB * 18)),
                       "r"((unsigned)TILE_BYTES), "r"(mbu)
                    : "memory");
            }
        }
    }
    if (tid == 0 && nt > 0)
        asm volatile("cp.async.bulk.wait_group 0;" ::: "memory");  // stores done

    // global remainder tile (B % SPB != 0): block 0, direct scalar path
    if (blockIdx.x == 0 && (B % SPB) != 0) {
        const int base = ntf * SPB;
        const int rem  = B - base;
        if (tid < rem) {
            float row[18];
            const float* src = z + (size_t)(base + tid) * 18;
            #pragma unroll
            for (int c = 0; c < 18; c++) row[c] = src[c];
            sample_row(row, s_tab, mi0, mi1, mi2);
            float* dst = out + (size_t)(base + tid) * 18;
            #pragma unroll
            for (int c = 0; c < 18; c++) dst[c] = row[c];
        }
    }
}

extern "C" void kernel_launch(void* const* d_in, const int* in_sizes, int n_in,
                              void* d_out, int out_size)
{
    const float* z     = (const float*)d_in[0];
    const float* log_m = (const float*)d_in[1];
    const float* W1    = (const float*)d_in[2];
    const float* b1    = (const float*)d_in[3];
    const float* W2    = (const float*)d_in[4];
    const float* b2    = (const float*)d_in[5];
    const float* W3    = (const float*)d_in[6];
    // d_in[7] = b3 drops out of the gradient
    float* out = (float*)d_out;
    const int B = in_sizes[0] / 18;

    const size_t smem = (128 * 129 + 128 + 128 + 4) * sizeof(float);  // 67088 B
    cudaFuncSetAttribute(build_table_kernel,
                         cudaFuncAttributeMaxDynamicSharedMemorySize, (int)smem);

    // primary: one block per table point
    build_table_kernel<<<TAB_N, 128, smem>>>(W1, b1, W2, b2, W3, log_m);

    // secondary with programmatic dependent launch: overlaps primary
    const int ntf  = B / SPB;                            // 2048 full tiles
    const int grid = max(1, (ntf + TPB - 1) / TPB);      // 512

    cudaLaunchAttribute attrs[1];
    attrs[0].id = cudaLaunchAttributeProgrammaticStreamSerialization;
    attrs[0].val.programmaticStreamSerializationAllowed = 1;

    cudaLaunchConfig_t cfg = {};
    cfg.gridDim  = dim3(grid, 1, 1);
    cfg.blockDim = dim3(BLK, 1, 1);
    cfg.dynamicSmemBytes = 0;
    cfg.stream = 0;
    cfg.attrs = attrs;
    cfg.numAttrs = 1;

    cudaLaunchKernelEx(&cfg, hnn_kernel, z, out, B);
}